// round 5
// baseline (speedup 1.0000x reference)
#include <cuda_runtime.h>
#include <math.h>

#define HH 192
#define WW 192
#define OH 182
#define OW 182
#define OHW (OH*OW)
#define NB 8
#define NC 64
#define NF 3

#define SSIM_C1 0.01f
#define SSIM_C2 0.09f

// 11-tap gaussian (sigma=1.5), normalized
#define GW0 0.00102838f
#define GW1 0.00759876f
#define GW2 0.03600077f
#define GW3 0.10936069f
#define GW4 0.21300554f
#define GW5 0.26601173f

typedef unsigned long long u64t;

// ---- packed f32x2 helpers (Blackwell paired-FP32 pipe) ----
__device__ __forceinline__ u64t FMA2(u64t a, u64t b, u64t c) {
    u64t d; asm("fma.rn.f32x2 %0, %1, %2, %3;" : "=l"(d) : "l"(a), "l"(b), "l"(c)); return d;
}
__device__ __forceinline__ u64t PK(float x, float y) {
    u64t v; asm("mov.b64 %0, {%1, %2};" : "=l"(v) : "f"(x), "f"(y)); return v;
}
__device__ __forceinline__ float2 UPK(u64t v) {
    float2 f; asm("mov.b64 {%0, %1}, %2;" : "=f"(f.x), "=f"(f.y) : "l"(v)); return f;
}

// __device__ scratch (allocation-free rule)
__device__ float2 g_mf [NB*NF*OH*OW];    // {mu_f, sig_f}
__device__ float  g_part[2][NB*NF*NC];   // per-strip ssim partial sums

// ---------------------------------------------------------------------------
// Kernel 1: per-(b,f) gaussian moments {mu_f, sig_f}. Grid (14 strips, 24 ch).
// ---------------------------------------------------------------------------
__global__ void __launch_bounds__(192) f_moments_kernel(const float* __restrict__ f)
{
    const int s   = blockIdx.x;          // row strip 0..13 (13 output rows each)
    const int bj  = blockIdx.y;          // 0..23  (b*3+j)
    const int tid = threadIdx.x;         // 0..191
    const float* fp = f + (size_t)bj * HH * WW;
    const int o0   = s * 13;
    const int o1   = min(OH, o0 + 13);   // exclusive
    const int rend = o1 + 9;             // last input row (inclusive)

    __shared__ float2 sp[2][192];

    const u64t wp0 = PK(GW0,GW0), wp1 = PK(GW1,GW1), wp2 = PK(GW2,GW2);
    const u64t wp3 = PK(GW3,GW3), wp4 = PK(GW4,GW4), wp5 = PK(GW5,GW5);

    u64t rM[11];
#pragma unroll
    for (int i = 0; i < 11; ++i) rM[i] = 0ull;

    float fv = fp[o0 * WW + tid];
    for (int r = o0; r <= rend; ++r) {
        const int buf = r & 1;
        sp[buf][tid] = make_float2(fv, fv * fv);
        float nfv = 0.f;
        if (r < rend) nfv = fp[(r + 1) * WW + tid];
        __syncthreads();
        if (tid < OW) {
            const u64t* spp = reinterpret_cast<const u64t*>(sp[buf]);
            u64t hh = 0ull;
#define K1H(k, WP) { u64t q = spp[tid + (k)]; hh = FMA2(WP, q, hh); }
            K1H(0,wp0) K1H(1,wp1) K1H(2,wp2) K1H(3,wp3) K1H(4,wp4) K1H(5,wp5)
            K1H(6,wp4) K1H(7,wp3) K1H(8,wp2) K1H(9,wp1) K1H(10,wp0)
#undef K1H
#pragma unroll
            for (int j = 10; j >= 1; --j) rM[j] = rM[j-1];
            rM[0] = 0ull;
#define K1A(j, WP) { rM[j] = FMA2(WP, hh, rM[j]); }
            K1A(0,wp0) K1A(1,wp1) K1A(2,wp2) K1A(3,wp3) K1A(4,wp4) K1A(5,wp5)
            K1A(6,wp4) K1A(7,wp3) K1A(8,wp2) K1A(9,wp1) K1A(10,wp0)
#undef K1A
            if (r - 10 >= o0) {
                const int o = r - 10;
                const float2 mv = UPK(rM[10]);
                g_mf[bj * OHW + o * OW + tid] = make_float2(mv.x, mv.y - mv.x*mv.x);
            }
        }
        fv = nfv;
    }
}

// ---------------------------------------------------------------------------
// Kernel 2: main SSIM, warp-specialized two-team version with f32x2 math.
// Grid (512, 2): blockIdx.x = b*64+c, blockIdx.y = row half (91 out rows).
// Team X (tid<192) blurs packed {x, x^2}; team F blurs packed {f0x,f1x} + f2x
// and computes SSIM using team X's {mu_x, sig_x} exchange from the PREVIOUS
// row (one __syncthreads per row). Rings are f32x2-packed register arrays.
// ---------------------------------------------------------------------------

// ring slot for output row (q - t), q = within-strip phase, PH = q mod 11
#define RS(PH,t) (((PH) + 22 - (t)) % 11)

#define HTX(t,WP) { u64t q = bx2[c + (t)]; hAB = FMA2(WP, q, hAB); }

#define HTF(t,WP,GS) { const float4 q = bf[c + (t)]; \
    hCD = FMA2(WP, PK(q.x, q.y), hCD); h4 = fmaf((GS), q.z, h4); }

#define VTX(PH,t,WP,WARMF) { if (!(WARMF) || (PH) >= (t)) { \
    rAB[RS(PH,t)] = FMA2(WP, hAB, rAB[RS(PH,t)]); } }

#define VTF(PH,t,WP,GS,WARMF) { if (!(WARMF) || (PH) >= (t)) { \
    rAB[RS(PH,t)] = FMA2(WP, hCD, rAB[RS(PH,t)]); \
    rD[RS(PH,t)]  = fmaf((GS), h4, rD[RS(PH,t)]); } }

#define VX(PH,W) VTX(PH,0,wp0,W) VTX(PH,1,wp1,W) VTX(PH,2,wp2,W) VTX(PH,3,wp3,W) \
                 VTX(PH,4,wp4,W) VTX(PH,5,wp5,W) VTX(PH,6,wp4,W) VTX(PH,7,wp3,W) \
                 VTX(PH,8,wp2,W) VTX(PH,9,wp1,W) VTX(PH,10,wp0,W)
#define VF(PH,W) VTF(PH,0,wp0,GW0,W) VTF(PH,1,wp1,GW1,W) VTF(PH,2,wp2,GW2,W) \
                 VTF(PH,3,wp3,GW3,W) VTF(PH,4,wp4,GW4,W) VTF(PH,5,wp5,GW5,W) \
                 VTF(PH,6,wp4,GW4,W) VTF(PH,7,wp3,GW3,W) VTF(PH,8,wp2,GW2,W) \
                 VTF(PH,9,wp1,GW1,W) VTF(PH,10,wp0,GW0,W)

#define SSJ(MU,SG,P,S) { \
    const float mm  = (MU) * mux; \
    const float num = (2.f*mm + SSIM_C1) * (2.f*((P) - mm) + SSIM_C2); \
    const float den = (fmaf((MU),(MU),mux2) + SSIM_C1) * ((SG) + c2s); \
    S += __fdividef(num, den); }

#define ROW(PH, WARMF) { \
    const int r = rbase + (PH); \
    if (r < rend) { \
        const int buf = r & 1; \
        if (isX) { \
            sx2[buf][c] = make_float2(v0, v0*v0); \
            n0 = 0.f; \
            if (r + 1 < rend) n0 = xp[(r+1)*WW + c]; \
        } else { \
            sf[buf][c] = make_float4(v1*v0, v2*v0, v3*v0, 0.f); \
            n0 = 0.f; n1 = 0.f; n2 = 0.f; n3 = 0.f; \
            if (r + 1 < rend) { const int no = (r+1)*WW + c; \
                n0 = xp[no]; n1 = fq0[no]; n2 = fq1[no]; n3 = fq2[no]; } \
            if ((!(WARMF) || (PH) >= 10) && c < OW) { \
                const int mbase = (r-10)*OW + c; \
                nm0 = g_mf[mb0+mbase]; nm1 = g_mf[mb1+mbase]; nm2 = g_mf[mb2+mbase]; } \
        } \
        __syncthreads(); \
        if (c < OW) { \
            if (isX) { \
                u64t hAB = 0ull; \
                const u64t* bx2 = reinterpret_cast<const u64t*>(sx2[buf]); \
                HTX(0,wp0) HTX(1,wp1) HTX(2,wp2) HTX(3,wp3) HTX(4,wp4) HTX(5,wp5) \
                HTX(6,wp4) HTX(7,wp3) HTX(8,wp2) HTX(9,wp1) HTX(10,wp0) \
                VX(PH, WARMF) \
                if (!(WARMF) || (PH) == 10) { \
                    const int e = ((PH)+1) % 11; \
                    const float2 mv = UPK(rAB[e]); \
                    sex[buf][c] = make_float2(mv.x, mv.y - mv.x*mv.x); \
                    rAB[e] = 0ull; } \
            } else { \
                u64t hCD = 0ull; float h4 = 0.f; \
                const float4* bf = sf[buf]; \
                HTF(0,wp0,GW0) HTF(1,wp1,GW1) HTF(2,wp2,GW2) HTF(3,wp3,GW3) \
                HTF(4,wp4,GW4) HTF(5,wp5,GW5) HTF(6,wp4,GW4) HTF(7,wp3,GW3) \
                HTF(8,wp2,GW2) HTF(9,wp1,GW1) HTF(10,wp0,GW0) \
                VF(PH, WARMF) \
                if (!(WARMF)) { \
                    const float2 ex = sex[buf ^ 1][c]; \
                    const float mux = ex.x, mux2 = ex.x*ex.x, c2s = ex.y + SSIM_C2; \
                    SSJ(m0.x, m0.y, p0, s0) \
                    SSJ(m1.x, m1.y, p1, s1) \
                    SSJ(m2.x, m2.y, p2, s2) } \
                if (!(WARMF) || (PH) == 10) { \
                    const int e = ((PH)+1) % 11; \
                    const float2 pv = UPK(rAB[e]); \
                    p0 = pv.x; p1 = pv.y; p2 = rD[e]; \
                    rAB[e] = 0ull; rD[e] = 0.f; \
                    m0 = nm0; m1 = nm1; m2 = nm2; } \
            } \
        } \
        if (isX) { v0 = n0; } else { v0 = n0; v1 = n1; v2 = n2; v3 = n3; } \
    } }

__global__ void __launch_bounds__(384, 2) ssim_main_kernel(
    const float* __restrict__ x, const float* __restrict__ f)
{
    const int bc  = blockIdx.x;          // b*64 + c
    const int b   = bc >> 6;
    const int ch  = bc & 63;
    const int tid = threadIdx.x;
    const bool isX = tid < 192;
    const int c   = isX ? tid : tid - 192;

    const int r0s  = blockIdx.y * 91;    // strip input start
    const int rend = r0s + 101;          // strip input end (exclusive)

    const float* xp  = x + (size_t)bc * HH * WW;
    const float* fq0 = f + (size_t)(b*3 + 0) * HH * WW;
    const float* fq1 = f + (size_t)(b*3 + 1) * HH * WW;
    const float* fq2 = f + (size_t)(b*3 + 2) * HH * WW;
    const int mb0 = (b*3 + 0) * OHW;
    const int mb1 = (b*3 + 1) * OHW;
    const int mb2 = (b*3 + 2) * OHW;

    __shared__ float2 sx2[2][192];
    __shared__ float4 sf [2][192];
    __shared__ float2 sex[2][192];       // exchange {mu_x, sig_x}
    __shared__ float  wredF[6][3];

    const u64t wp0 = PK(GW0,GW0), wp1 = PK(GW1,GW1), wp2 = PK(GW2,GW2);
    const u64t wp3 = PK(GW3,GW3), wp4 = PK(GW4,GW4), wp5 = PK(GW5,GW5);

    // overlaid vertical rings: X uses rAB ({x,x^2}); F uses rAB ({f0x,f1x}) + rD (f2x)
    u64t rAB[11]; float rD[11];
#pragma unroll
    for (int i = 0; i < 11; ++i) { rAB[i] = 0ull; rD[i] = 0.f; }

    float v0 = 0.f, v1 = 0.f, v2 = 0.f, v3 = 0.f;
    float n0 = 0.f, n1 = 0.f, n2 = 0.f, n3 = 0.f;
    float p0 = 0.f, p1 = 0.f, p2 = 0.f;
    float2 m0 = make_float2(0.f,0.f), m1 = m0, m2 = m0;
    float2 nm0 = m0, nm1 = m0, nm2 = m0;
    float s0 = 0.f, s1 = 0.f, s2 = 0.f;

    // preload strip first row
    if (isX) {
        v0 = xp[r0s*WW + c];
    } else {
        const int o = r0s*WW + c;
        v0 = xp[o]; v1 = fq0[o]; v2 = fq1[o]; v3 = fq2[o];
    }

    {   // warm-up 11 rows (compile-time pruned ring guards; no SSIM consume)
        const int rbase = r0s;
        ROW(0,1) ROW(1,1) ROW(2,1) ROW(3,1) ROW(4,1) ROW(5,1)
        ROW(6,1) ROW(7,1) ROW(8,1) ROW(9,1) ROW(10,1)
    }
    for (int rbase = r0s + 11; rbase < rend; rbase += 11) {
        ROW(0,0) ROW(1,0) ROW(2,0) ROW(3,0) ROW(4,0) ROW(5,0)
        ROW(6,0) ROW(7,0) ROW(8,0) ROW(9,0) ROW(10,0)
    }

    // flush: consume the last pending output row (uses sex written at rend-1)
    __syncthreads();
    if (!isX && c < OW) {
        const float2 ex = sex[(rend-1) & 1][c];
        const float mux = ex.x, mux2 = ex.x*ex.x, c2s = ex.y + SSIM_C2;
        SSJ(m0.x, m0.y, p0, s0)
        SSJ(m1.x, m1.y, p1, s1)
        SSJ(m2.x, m2.y, p2, s2)
    }

    // reduce the 3 sums over team F; write per-strip partial (no atomics)
    if (!isX) {
        const float inv = 1.0f / (float)(OH * OW);
        float t0 = s0 * inv, t1 = s1 * inv, t2 = s2 * inv;
#pragma unroll
        for (int off = 16; off; off >>= 1) {
            t0 += __shfl_down_sync(0xFFFFFFFFu, t0, off);
            t1 += __shfl_down_sync(0xFFFFFFFFu, t1, off);
            t2 += __shfl_down_sync(0xFFFFFFFFu, t2, off);
        }
        const int fw = (tid - 192) >> 5, lane = tid & 31;
        if (lane == 0) { wredF[fw][0] = t0; wredF[fw][1] = t1; wredF[fw][2] = t2; }
    }
    __syncthreads();
    if (tid == 192) {
        float q0 = 0.f, q1 = 0.f, q2 = 0.f;
#pragma unroll
        for (int w = 0; w < 6; ++w) { q0 += wredF[w][0]; q1 += wredF[w][1]; q2 += wredF[w][2]; }
        g_part[blockIdx.y][(b*3 + 0)*NC + ch] = q0;
        g_part[blockIdx.y][(b*3 + 1)*NC + ch] = q1;
        g_part[blockIdx.y][(b*3 + 2)*NC + ch] = q2;
    }
}

// ---------------------------------------------------------------------------
// Kernel 3: sum strip partials; emit ssim_info to out[512:2048]; spatial gate
// conv (3,1) over C, relu, MLP 64->64->64, sigmoid -> out[0:512].
// ---------------------------------------------------------------------------
__global__ void __launch_bounds__(64) epilogue_kernel(
    const float* __restrict__ sw,
    const float* __restrict__ W1, const float* __restrict__ b1,
    const float* __restrict__ W2, const float* __restrict__ b2,
    float* __restrict__ out, int out_size)
{
    const int b = blockIdx.x;
    const int c = threadIdx.x;

    __shared__ float ss[3][66];     // zero-padded ssim_info for this b
    __shared__ float gate[64];
    __shared__ float h1s[64];

#pragma unroll
    for (int j = 0; j < 3; ++j) {
        const int idx = (b*3 + j)*NC + c;
        const float sj = g_part[0][idx] + g_part[1][idx];
        ss[j][c + 1] = sj;
        if (out_size >= 2048) out[512 + b*NF*NC + j*NC + c] = sj;
        if (c == 0)  ss[j][0]  = 0.f;
        if (c == 63) ss[j][65] = 0.f;
    }
    __syncthreads();

    float g = 0.f;
#pragma unroll
    for (int j = 0; j < 3; ++j)
#pragma unroll
        for (int d = 0; d < 3; ++d)
            g = fmaf(sw[j*3 + d], ss[j][c + d], g);
    gate[c] = fmaxf(g, 0.f);
    __syncthreads();

    float h1 = b1[c];
#pragma unroll 8
    for (int k = 0; k < 64; ++k) h1 = fmaf(W1[c*64 + k], gate[k], h1);
    h1s[c] = fmaxf(h1, 0.f);
    __syncthreads();

    float h2 = b2[c];
#pragma unroll 8
    for (int k = 0; k < 64; ++k) h2 = fmaf(W2[c*64 + k], h1s[k], h2);
    out[b*64 + c] = 1.0f / (1.0f + expf(-h2));
}

// ---------------------------------------------------------------------------
extern "C" void kernel_launch(void* const* d_in, const int* in_sizes, int n_in,
                              void* d_out, int out_size)
{
    const float* x  = (const float*)d_in[0];
    const float* f  = (const float*)d_in[1];
    const float* sw = (const float*)d_in[2];
    const float* W1 = (const float*)d_in[3];
    const float* b1 = (const float*)d_in[4];
    const float* W2 = (const float*)d_in[5];
    const float* b2 = (const float*)d_in[6];
    float* out = (float*)d_out;

    f_moments_kernel<<<dim3(14, 24), 192>>>(f);
    ssim_main_kernel<<<dim3(NB*NC, 2), 384>>>(x, f);
    epilogue_kernel<<<NB, 64>>>(sw, W1, b1, W2, b2, out, out_size);
}

// round 6
// speedup vs baseline: 1.0343x; 1.0343x over previous
#include <cuda_runtime.h>
#include <math.h>

#define HH 192
#define WW 192
#define OH 182
#define OW 182
#define OHW (OH*OW)
#define NB 8
#define NC 64
#define NF 3
#define FOFF (HH*WW)

#define SSIM_C1 0.01f
#define SSIM_C2 0.09f

// 11-tap gaussian (sigma=1.5), normalized; literals so blur FMAs compile to
// FFMA with immediate multiplier (rt_SMSP = 1 on sm_10x).
#define GW0 0.00102838f
#define GW1 0.00759876f
#define GW2 0.03600077f
#define GW3 0.10936069f
#define GW4 0.21300554f
#define GW5 0.26601173f

#define TAPS(M) M(0,GW0) M(1,GW1) M(2,GW2) M(3,GW3) M(4,GW4) M(5,GW5) \
                M(6,GW4) M(7,GW3) M(8,GW2) M(9,GW1) M(10,GW0)

// __device__ scratch (allocation-free rule)
__device__ float2 g_mf [NB*NF*OH*OW];    // {mu_f, sig_f}
__device__ float  g_part[2][NB*NF*NC];   // per-strip ssim partial sums

// ---------------------------------------------------------------------------
// Kernel 1: per-(b,f) gaussian moments {mu_f, sig_f}. Grid (14 strips, 24 ch).
// ---------------------------------------------------------------------------
__global__ void __launch_bounds__(192) f_moments_kernel(const float* __restrict__ f)
{
    const int s   = blockIdx.x;          // row strip 0..13 (13 output rows each)
    const int bj  = blockIdx.y;          // 0..23  (b*3+j)
    const int tid = threadIdx.x;         // 0..191
    const float* fp = f + (size_t)bj * HH * WW;
    const int o0   = s * 13;
    const int o1   = min(OH, o0 + 13);   // exclusive
    const int rend = o1 + 9;             // last input row (inclusive)

    __shared__ float2 sp[2][192];
    float a0[11], a1[11];
#pragma unroll
    for (int i = 0; i < 11; ++i) { a0[i] = 0.f; a1[i] = 0.f; }

    float fv = fp[o0 * WW + tid];
    for (int r = o0; r <= rend; ++r) {
        const int buf = r & 1;
        sp[buf][tid] = make_float2(fv, fv * fv);
        float nfv = 0.f;
        if (r < rend) nfv = fp[(r + 1) * WW + tid];
        __syncthreads();
        if (tid < OW) {
            const float2* spb = sp[buf];
            float h0 = 0.f, h1 = 0.f;
#define K1H(k, GK) { float2 q = spb[tid + (k)]; h0 = fmaf((GK), q.x, h0); h1 = fmaf((GK), q.y, h1); }
            TAPS(K1H)
#undef K1H
#pragma unroll
            for (int j = 10; j >= 1; --j) { a0[j] = a0[j-1]; a1[j] = a1[j-1]; }
            a0[0] = 0.f; a1[0] = 0.f;
#define K1A(j, GJ) { a0[j] = fmaf((GJ), h0, a0[j]); a1[j] = fmaf((GJ), h1, a1[j]); }
            TAPS(K1A)
#undef K1A
            if (r - 10 >= o0) {
                const int o = r - 10;
                const float mu = a0[10];
                g_mf[bj * OHW + o * OW + tid] = make_float2(mu, a1[10] - mu * mu);
            }
        }
        fv = nfv;
    }
}

// ---------------------------------------------------------------------------
// Kernel 2: main SSIM, warp-specialized two-team, 2-row pairs (1 sync / 2 rows).
// Grid (512, 2): blockIdx.x = b*64+c; blockIdx.y = strip (inputs 0..101 / 92..191).
// Team X (tid<192) blurs {x,x^2}; team F blurs {f_j x} and consumes SSIM with a
// one-pair lag via pending registers. Ring slots are compile-time (mod-11 of
// literal phase); chunks of 11 pairs keep phases aligned (q ≡ 1 mod 11).
// ---------------------------------------------------------------------------

#define RSA(QQ,t) (((QQ)+22-(t))%11)

#define SSJ(MU,SG,P,S) { \
    const float mm  = (MU) * mux; \
    const float num = (2.f*mm + SSIM_C1) * (2.f*((P) - mm) + SSIM_C2); \
    const float den = (fmaf((MU),(MU),mux2) + SSIM_C1) * ((SG) + c2s); \
    S += __fdividef(num, den); }

#define XROW(QQ, SL, WARM) { \
    float h0 = 0.f, h1 = 0.f; \
    { const float2* bp = sx2[pb][SL]; \
      TAPS(XH_) } \
    TAPS(XV_##QQ##_unused) \
    if (!(WARM) || (QQ) >= 10) { \
        const int e = ((QQ)+1) % 11; \
        const float mu = ringA[e]; \
        sex[pb][SL][c] = make_float2(mu, ringB[e] - mu*mu); \
        ringA[e] = 0.f; ringB[e] = 0.f; } }

// (TAPS can't take extra params through ##; define XROW/FROW explicitly)
#undef XROW

#define XH_(k,G) { float2 q = bp[c + (k)]; h0 = fmaf((G), q.x, h0); h1 = fmaf((G), q.y, h1); }
#define FH_(k,G) { float4 q = bp[c + (k)]; h2 = fmaf((G), q.x, h2); \
                   h3 = fmaf((G), q.y, h3); h4 = fmaf((G), q.z, h4); }

#define XROW(QQ, SL, WARM) { \
    float h0 = 0.f, h1 = 0.f; \
    { const float2* bp = sx2[pb][SL]; TAPS(XH_) } \
_Pragma("unroll") \
    { } \
    /* vertical taps */ \
    { \
      _XV(QQ,0,GW0,WARM) _XV(QQ,1,GW1,WARM) _XV(QQ,2,GW2,WARM) _XV(QQ,3,GW3,WARM) \
      _XV(QQ,4,GW4,WARM) _XV(QQ,5,GW5,WARM) _XV(QQ,6,GW4,WARM) _XV(QQ,7,GW3,WARM) \
      _XV(QQ,8,GW2,WARM) _XV(QQ,9,GW1,WARM) _XV(QQ,10,GW0,WARM) \
    } \
    if (!(WARM) || (QQ) >= 10) { \
        const int e = ((QQ)+1) % 11; \
        const float mu = ringA[e]; \
        sex[pb][SL][c] = make_float2(mu, ringB[e] - mu*mu); \
        ringA[e] = 0.f; ringB[e] = 0.f; } }

#define _XV(QQ,t,G,W) { if (!(W) || (QQ) >= (t)) { \
    ringA[RSA(QQ,t)] = fmaf((G), h0, ringA[RSA(QQ,t)]); \
    ringB[RSA(QQ,t)] = fmaf((G), h1, ringB[RSA(QQ,t)]); } }

#define _FV(QQ,t,G,W) { if (!(W) || (QQ) >= (t)) { \
    ringA[RSA(QQ,t)] = fmaf((G), h2, ringA[RSA(QQ,t)]); \
    ringB[RSA(QQ,t)] = fmaf((G), h3, ringB[RSA(QQ,t)]); \
    ringD[RSA(QQ,t)] = fmaf((G), h4, ringD[RSA(QQ,t)]); } }

#define FROW(QQ, SL, WARM) { \
    float h2 = 0.f, h3 = 0.f, h4 = 0.f; \
    { const float4* bp = sf[pb][SL]; TAPS(FH_) } \
    { \
      _FV(QQ,0,GW0,WARM) _FV(QQ,1,GW1,WARM) _FV(QQ,2,GW2,WARM) _FV(QQ,3,GW3,WARM) \
      _FV(QQ,4,GW4,WARM) _FV(QQ,5,GW5,WARM) _FV(QQ,6,GW4,WARM) _FV(QQ,7,GW3,WARM) \
      _FV(QQ,8,GW2,WARM) _FV(QQ,9,GW1,WARM) _FV(QQ,10,GW0,WARM) \
    } \
    if (!(WARM) || (QQ) >= 10) { \
        const int e = ((QQ)+1) % 11; \
        const int ob = (rA + (SL) - 10)*OW + c; \
        if ((SL) == 0) { \
            ppa0 = ringA[e]; ppa1 = ringB[e]; ppa2 = ringD[e]; \
            pma0 = g_mf[fo0 + ob]; pma1 = g_mf[fo0 + OHW + ob]; pma2 = g_mf[fo0 + 2*OHW + ob]; \
        } else { \
            ppb0 = ringA[e]; ppb1 = ringB[e]; ppb2 = ringD[e]; \
            pmb0 = g_mf[fo0 + ob]; pmb1 = g_mf[fo0 + OHW + ob]; pmb2 = g_mf[fo0 + 2*OHW + ob]; \
        } \
        ringA[e] = 0.f; ringB[e] = 0.f; ringD[e] = 0.f; } }

#define CONSUME { \
    { const float2 ex = sex[pb^1][0][c]; \
      const float mux = ex.x, mux2 = ex.x*ex.x, c2s = ex.y + SSIM_C2; \
      SSJ(pma0.x, pma0.y, ppa0, s0) SSJ(pma1.x, pma1.y, ppa1, s1) SSJ(pma2.x, pma2.y, ppa2, s2) } \
    { const float2 ex = sex[pb^1][1][c]; \
      const float mux = ex.x, mux2 = ex.x*ex.x, c2s = ex.y + SSIM_C2; \
      SSJ(pmb0.x, pmb0.y, ppb0, s0) SSJ(pmb1.x, pmb1.y, ppb1, s1) SSJ(pmb2.x, pmb2.y, ppb2, s2) } }

#define PAIR(QQ, WARM) { \
    if (isX) { \
        sx2[pb][0][c] = make_float2(vx0, vx0*vx0); \
        sx2[pb][1][c] = make_float2(vx1, vx1*vx1); \
        vx0 = (rA+2 < rendA) ? xp[(rA+2)*WW + c] : 0.f; \
        vx1 = (rA+3 < rendA) ? xp[(rA+3)*WW + c] : 0.f; \
    } else { \
        sf[pb][0][c] = make_float4(va1*va0, va2*va0, va3*va0, 0.f); \
        sf[pb][1][c] = make_float4(vb1*vb0, vb2*vb0, vb3*vb0, 0.f); \
        if (rA+2 < rendA) { const int o = (rA+2)*WW + c; \
            va0 = xp[o]; va1 = fp[o]; va2 = fp[o+FOFF]; va3 = fp[o+2*FOFF]; } \
        if (rA+3 < rendA) { const int o = (rA+3)*WW + c; \
            vb0 = xp[o]; vb1 = fp[o]; vb2 = fp[o+FOFF]; vb3 = fp[o+2*FOFF]; } \
    } \
    __syncthreads(); \
    if (c < OW) { \
        if (isX) { XROW(QQ, 0, WARM) XROW((QQ)+1, 1, WARM) } \
        else { \
            if (!(WARM)) CONSUME \
            FROW(QQ, 0, WARM) FROW((QQ)+1, 1, WARM) \
        } \
    } \
    pb ^= 1; rA += 2; }

__global__ void __launch_bounds__(384, 2) ssim_main_kernel(
    const float* __restrict__ x, const float* __restrict__ f)
{
    const int bc  = blockIdx.x;          // b*64 + c
    const int b   = bc >> 6;
    const int ch  = bc & 63;
    const int tid = threadIdx.x;
    const bool isX = tid < 192;
    const int c   = isX ? tid : tid - 192;

    const int r0    = (blockIdx.y == 0) ? 0   : 92;   // strip input start
    const int rendA = (blockIdx.y == 0) ? 102 : 192;  // strip input end (excl)

    const float* xp = x + (size_t)bc * HH * WW;
    const float* fp = f + (size_t)(b*3) * HH * WW;
    const int fo0 = (b*3) * OHW;

    __shared__ float2 sx2[2][2][192];
    __shared__ float4 sf [2][2][192];
    __shared__ float2 sex[2][2][192];    // exchange {mu_x, sig_x} per pair-row
    __shared__ float  wredF[6][3];

    float ringA[11], ringB[11], ringD[11];
#pragma unroll
    for (int i = 0; i < 11; ++i) { ringA[i] = 0.f; ringB[i] = 0.f; ringD[i] = 0.f; }

    float vx0 = 0.f, vx1 = 0.f;
    float va0 = 0.f, va1 = 0.f, va2 = 0.f, va3 = 0.f;
    float vb0 = 0.f, vb1 = 0.f, vb2 = 0.f, vb3 = 0.f;
    float ppa0 = 0.f, ppa1 = 0.f, ppa2 = 0.f, ppb0 = 0.f, ppb1 = 0.f, ppb2 = 0.f;
    float2 pma0 = make_float2(0.f,0.f), pma1 = pma0, pma2 = pma0;
    float2 pmb0 = pma0, pmb1 = pma0, pmb2 = pma0;
    float s0 = 0.f, s1 = 0.f, s2 = 0.f;
    int rA = r0, pb = 0;

    // preload first two rows
    if (isX) {
        vx0 = xp[r0*WW + c];
        vx1 = xp[(r0+1)*WW + c];
    } else {
        { const int o = r0*WW + c;     va0 = xp[o]; va1 = fp[o]; va2 = fp[o+FOFF]; va3 = fp[o+2*FOFF]; }
        { const int o = (r0+1)*WW + c; vb0 = xp[o]; vb1 = fp[o]; vb2 = fp[o+FOFF]; vb3 = fp[o+2*FOFF]; }
    }

    // warm-up: 6 pairs (rows q=0..11); emits at q=10,11; no consumption
    PAIR(0,1) PAIR(2,1) PAIR(4,1) PAIR(6,1) PAIR(8,1) PAIR(10,1)

    // main: chunks of 11 pairs (22 rows); q ≡ 1 (mod 11) at every chunk start
#pragma unroll 1
    for (int chunk = 0; chunk < 4; ++chunk) {
        PAIR(12,0) PAIR(14,0) PAIR(16,0) PAIR(18,0) PAIR(20,0) PAIR(22,0)
        PAIR(24,0) PAIR(26,0) PAIR(28,0) PAIR(30,0) PAIR(32,0)
    }
    // tail pair (strip 0 only: rows q=100,101 ≡ phases 1,2 mod 11)
    if (rA < rendA) { PAIR(12,0) }

    // flush: consume the final pair's pending outputs
    __syncthreads();
    if (!isX && c < OW) CONSUME

    // reduce the 3 sums over team F; write per-strip partial (no atomics)
    if (!isX) {
        const float inv = 1.0f / (float)(OH * OW);
        float t0 = s0 * inv, t1 = s1 * inv, t2 = s2 * inv;
#pragma unroll
        for (int off = 16; off; off >>= 1) {
            t0 += __shfl_down_sync(0xFFFFFFFFu, t0, off);
            t1 += __shfl_down_sync(0xFFFFFFFFu, t1, off);
            t2 += __shfl_down_sync(0xFFFFFFFFu, t2, off);
        }
        const int fw = (tid - 192) >> 5, lane = tid & 31;
        if (lane == 0) { wredF[fw][0] = t0; wredF[fw][1] = t1; wredF[fw][2] = t2; }
    }
    __syncthreads();
    if (tid == 192) {
        float q0 = 0.f, q1 = 0.f, q2 = 0.f;
#pragma unroll
        for (int w = 0; w < 6; ++w) { q0 += wredF[w][0]; q1 += wredF[w][1]; q2 += wredF[w][2]; }
        g_part[blockIdx.y][(b*3 + 0)*NC + ch] = q0;
        g_part[blockIdx.y][(b*3 + 1)*NC + ch] = q1;
        g_part[blockIdx.y][(b*3 + 2)*NC + ch] = q2;
    }
}

// ---------------------------------------------------------------------------
// Kernel 3: sum strip partials; emit ssim_info to out[512:2048]; spatial gate
// conv (3,1) over C, relu, MLP 64->64->64 (float4 weight loads), sigmoid.
// ---------------------------------------------------------------------------
__global__ void __launch_bounds__(64) epilogue_kernel(
    const float* __restrict__ sw,
    const float* __restrict__ W1, const float* __restrict__ b1,
    const float* __restrict__ W2, const float* __restrict__ b2,
    float* __restrict__ out, int out_size)
{
    const int b = blockIdx.x;
    const int c = threadIdx.x;

    __shared__ float ss[3][66];     // zero-padded ssim_info for this b
    __shared__ float gate[64];
    __shared__ float h1s[64];

#pragma unroll
    for (int j = 0; j < 3; ++j) {
        const int idx = (b*3 + j)*NC + c;
        const float sj = g_part[0][idx] + g_part[1][idx];
        ss[j][c + 1] = sj;
        if (out_size >= 2048) out[512 + b*NF*NC + j*NC + c] = sj;
        if (c == 0)  ss[j][0]  = 0.f;
        if (c == 63) ss[j][65] = 0.f;
    }
    __syncthreads();

    float g = 0.f;
#pragma unroll
    for (int j = 0; j < 3; ++j)
#pragma unroll
        for (int d = 0; d < 3; ++d)
            g = fmaf(sw[j*3 + d], ss[j][c + d], g);
    gate[c] = fmaxf(g, 0.f);
    __syncthreads();

    const float4* W1v = reinterpret_cast<const float4*>(W1);
    float h1 = b1[c];
#pragma unroll
    for (int k = 0; k < 16; ++k) {
        const float4 w = W1v[c*16 + k];
        h1 = fmaf(w.x, gate[4*k+0], h1); h1 = fmaf(w.y, gate[4*k+1], h1);
        h1 = fmaf(w.z, gate[4*k+2], h1); h1 = fmaf(w.w, gate[4*k+3], h1);
    }
    h1s[c] = fmaxf(h1, 0.f);
    __syncthreads();

    const float4* W2v = reinterpret_cast<const float4*>(W2);
    float h2 = b2[c];
#pragma unroll
    for (int k = 0; k < 16; ++k) {
        const float4 w = W2v[c*16 + k];
        h2 = fmaf(w.x, h1s[4*k+0], h2); h2 = fmaf(w.y, h1s[4*k+1], h2);
        h2 = fmaf(w.z, h1s[4*k+2], h2); h2 = fmaf(w.w, h1s[4*k+3], h2);
    }
    out[b*64 + c] = 1.0f / (1.0f + expf(-h2));
}

// ---------------------------------------------------------------------------
extern "C" void kernel_launch(void* const* d_in, const int* in_sizes, int n_in,
                              void* d_out, int out_size)
{
    const float* x  = (const float*)d_in[0];
    const float* f  = (const float*)d_in[1];
    const float* sw = (const float*)d_in[2];
    const float* W1 = (const float*)d_in[3];
    const float* b1 = (const float*)d_in[4];
    const float* W2 = (const float*)d_in[5];
    const float* b2 = (const float*)d_in[6];
    float* out = (float*)d_out;

    f_moments_kernel<<<dim3(14, 24), 192>>>(f);
    ssim_main_kernel<<<dim3(NB*NC, 2), 384>>>(x, f);
    epilogue_kernel<<<NB, 64>>>(sw, W1, b1, W2, b2, out, out_size);
}

// round 7
// speedup vs baseline: 1.0763x; 1.0406x over previous
#include <cuda_runtime.h>
#include <math.h>

#define HH 192
#define WW 192
#define OH 182
#define OW 182
#define OHW (OH*OW)
#define NB 8
#define NC 64
#define NF 3

#define SSIM_C1 0.01f
#define SSIM_C2 0.09f

// 11-tap gaussian (sigma=1.5), normalized; literals so blur FMAs compile to
// FFMA with immediate multiplier (rt_SMSP = 1 on sm_10x).
#define GW0 0.00102838f
#define GW1 0.00759876f
#define GW2 0.03600077f
#define GW3 0.10936069f
#define GW4 0.21300554f
#define GW5 0.26601173f

#define TAPS(M) M(0,GW0) M(1,GW1) M(2,GW2) M(3,GW3) M(4,GW4) M(5,GW5) \
                M(6,GW4) M(7,GW3) M(8,GW2) M(9,GW1) M(10,GW0)

// __device__ scratch (allocation-free rule)
__device__ float2 g_mf [NB*NF*OH*OW];    // {mu_f, sig_f}
__device__ float  g_part[2][NB*NF*NC];   // per-strip ssim partial sums

// ---------------------------------------------------------------------------
// Kernel 1: per-(b,f) gaussian moments {mu_f, sig_f}. Grid (14 strips, 24 ch).
// ---------------------------------------------------------------------------
__global__ void __launch_bounds__(192) f_moments_kernel(const float* __restrict__ f)
{
    const int s   = blockIdx.x;          // row strip 0..13 (13 output rows each)
    const int bj  = blockIdx.y;          // 0..23  (b*3+j)
    const int tid = threadIdx.x;         // 0..191
    const float* fp = f + (size_t)bj * HH * WW;
    const int o0   = s * 13;
    const int o1   = min(OH, o0 + 13);   // exclusive
    const int rend = o1 + 9;             // last input row (inclusive)

    __shared__ float2 sp[2][192];
    float a0[11], a1[11];
#pragma unroll
    for (int i = 0; i < 11; ++i) { a0[i] = 0.f; a1[i] = 0.f; }

    float fv = fp[o0 * WW + tid];
    for (int r = o0; r <= rend; ++r) {
        const int buf = r & 1;
        sp[buf][tid] = make_float2(fv, fv * fv);
        float nfv = 0.f;
        if (r < rend) nfv = fp[(r + 1) * WW + tid];
        __syncthreads();
        if (tid < OW) {
            const float2* spb = sp[buf];
            float h0 = 0.f, h1 = 0.f;
#define K1H(k, GK) { float2 q = spb[tid + (k)]; h0 = fmaf((GK), q.x, h0); h1 = fmaf((GK), q.y, h1); }
            TAPS(K1H)
#undef K1H
#pragma unroll
            for (int j = 10; j >= 1; --j) { a0[j] = a0[j-1]; a1[j] = a1[j-1]; }
            a0[0] = 0.f; a1[0] = 0.f;
#define K1A(j, GJ) { a0[j] = fmaf((GJ), h0, a0[j]); a1[j] = fmaf((GJ), h1, a1[j]); }
            TAPS(K1A)
#undef K1A
            if (r - 10 >= o0) {
                const int o = r - 10;
                const float mu = a0[10];
                g_mf[bj * OHW + o * OW + tid] = make_float2(mu, a1[10] - mu * mu);
            }
        }
        fv = nfv;
    }
}

// ---------------------------------------------------------------------------
// Kernel 2: main SSIM, balanced two-team warp specialization.
// Grid (512, 2): blockIdx.x = b*64+c, blockIdx.y = row strip (91 out rows).
// Team A (tid<192): blurs {x, x^2, f2*x} (float4 stage) and consumes SSIM j=2
//   locally at emit time (it owns mu_x/sig_x/blur(f2x)); publishes {mu_x,sig_x}.
// Team B: blurs {f0*x, f1*x} (float2 stage), consumes j=0,1 with one-row lag
//   via the exchange. One __syncthreads per row.
// ---------------------------------------------------------------------------

// ring slot for output row (q - t), q = within-strip phase, PH = q mod 11
#define RS(PH,t) (((PH) + 22 - (t)) % 11)

#define AH_(k,G) { float4 q = bp[c + (k)]; h0 = fmaf((G), q.x, h0); \
    h1 = fmaf((G), q.y, h1); h2 = fmaf((G), q.z, h2); }
#define BH_(k,G) { float2 q = bp[c + (k)]; h0 = fmaf((G), q.x, h0); \
    h1 = fmaf((G), q.y, h1); }

#define _AV(PH,t,G,W) { if (!(W) || (PH) >= (t)) { \
    ringA[RS(PH,t)] = fmaf((G), h0, ringA[RS(PH,t)]); \
    ringB[RS(PH,t)] = fmaf((G), h1, ringB[RS(PH,t)]); \
    ringC[RS(PH,t)] = fmaf((G), h2, ringC[RS(PH,t)]); } }

#define _BV(PH,t,G,W) { if (!(W) || (PH) >= (t)) { \
    ringA[RS(PH,t)] = fmaf((G), h0, ringA[RS(PH,t)]); \
    ringB[RS(PH,t)] = fmaf((G), h1, ringB[RS(PH,t)]); } }

#define AV(PH,W) _AV(PH,0,GW0,W) _AV(PH,1,GW1,W) _AV(PH,2,GW2,W) _AV(PH,3,GW3,W) \
                 _AV(PH,4,GW4,W) _AV(PH,5,GW5,W) _AV(PH,6,GW4,W) _AV(PH,7,GW3,W) \
                 _AV(PH,8,GW2,W) _AV(PH,9,GW1,W) _AV(PH,10,GW0,W)
#define BV(PH,W) _BV(PH,0,GW0,W) _BV(PH,1,GW1,W) _BV(PH,2,GW2,W) _BV(PH,3,GW3,W) \
                 _BV(PH,4,GW4,W) _BV(PH,5,GW5,W) _BV(PH,6,GW4,W) _BV(PH,7,GW3,W) \
                 _BV(PH,8,GW2,W) _BV(PH,9,GW1,W) _BV(PH,10,GW0,W)

#define SSJ(MU,SG,P,S) { \
    const float mm  = (MU) * mux; \
    const float num = (2.f*mm + SSIM_C1) * (2.f*((P) - mm) + SSIM_C2); \
    const float den = (fmaf((MU),(MU),mux2) + SSIM_C1) * ((SG) + c2s); \
    S += __fdividef(num, den); }

#define ROWM(PH, WARM) { \
    const int r = rbase + (PH); \
    if (r < rend) { \
        const int buf = r & 1; \
        if (isA) { \
            sA[buf][c] = make_float4(v0, v0*v0, v3*v0, 0.f); \
            n0 = 0.f; n3 = 0.f; \
            if (r + 1 < rend) { const int no = (r+1)*WW + c; \
                n0 = xp[no]; n3 = fq2[no]; } \
        } else { \
            sB[buf][c] = make_float2(v1*v0, v2*v0); \
            n0 = 0.f; n1 = 0.f; n2 = 0.f; \
            if (r + 1 < rend) { const int no = (r+1)*WW + c; \
                n0 = xp[no]; n1 = fq0[no]; n2 = fq1[no]; } \
            if ((!(WARM) || (PH) >= 10) && c < OW) { \
                const int ob = (r-10)*OW + c; \
                nm0 = g_mf[mb0+ob]; nm1 = g_mf[mb1+ob]; } \
        } \
        __syncthreads(); \
        if (c < OW) { \
            if (isA) { \
                float h0 = 0.f, h1 = 0.f, h2 = 0.f; \
                { const float4* bp = sA[buf]; TAPS(AH_) } \
                AV(PH, WARM) \
                if ((WARM) && (PH) == 9) m2 = g_mf[mb2 + (r-9)*OW + c]; \
                if (!(WARM) || (PH) == 10) { \
                    const int e = ((PH)+1) % 11; \
                    const float mu = ringA[e]; \
                    const float sg = ringB[e] - mu*mu; \
                    sex[buf][c] = make_float2(mu, sg); \
                    { const float mux = mu, mux2 = mu*mu, c2s = sg + SSIM_C2; \
                      SSJ(m2.x, m2.y, ringC[e], s2) } \
                    ringA[e] = 0.f; ringB[e] = 0.f; ringC[e] = 0.f; \
                    const int on = min(r - 9, OH - 1); \
                    m2 = g_mf[mb2 + on*OW + c]; \
                } \
            } else { \
                float h0 = 0.f, h1 = 0.f; \
                { const float2* bp = sB[buf]; TAPS(BH_) } \
                BV(PH, WARM) \
                if (!(WARM)) { \
                    const float2 ex = sex[buf ^ 1][c]; \
                    const float mux = ex.x, mux2 = ex.x*ex.x, c2s = ex.y + SSIM_C2; \
                    SSJ(m0.x, m0.y, p0, s0) \
                    SSJ(m1.x, m1.y, p1, s1) } \
                if (!(WARM) || (PH) == 10) { \
                    const int e = ((PH)+1) % 11; \
                    p0 = ringA[e]; p1 = ringB[e]; \
                    ringA[e] = 0.f; ringB[e] = 0.f; \
                    m0 = nm0; m1 = nm1; } \
            } \
        } \
        if (isA) { v0 = n0; v3 = n3; } else { v0 = n0; v1 = n1; v2 = n2; } \
    } }

__global__ void __launch_bounds__(384, 2) ssim_main_kernel(
    const float* __restrict__ x, const float* __restrict__ f)
{
    const int bc  = blockIdx.x;          // b*64 + c
    const int b   = bc >> 6;
    const int ch  = bc & 63;
    const int tid = threadIdx.x;
    const bool isA = tid < 192;
    const int c   = isA ? tid : tid - 192;

    const int r0s  = blockIdx.y * 91;    // strip input start
    const int rend = r0s + 101;          // strip input end (exclusive)

    const float* xp  = x + (size_t)bc * HH * WW;
    const float* fq0 = f + (size_t)(b*3 + 0) * HH * WW;
    const float* fq1 = f + (size_t)(b*3 + 1) * HH * WW;
    const float* fq2 = f + (size_t)(b*3 + 2) * HH * WW;
    const int mb0 = (b*3 + 0) * OHW;
    const int mb1 = (b*3 + 1) * OHW;
    const int mb2 = (b*3 + 2) * OHW;

    __shared__ float4 sA [2][192];       // {x, x^2, f2x, -}
    __shared__ float2 sB [2][192];       // {f0x, f1x}
    __shared__ float2 sex[2][192];       // exchange {mu_x, sig_x}
    __shared__ float  wredA[6];          // team-A s2 partials
    __shared__ float  wredB[6][2];       // team-B s0,s1 partials

    // vertical rings: A uses ringA(x), ringB(x^2), ringC(f2x); B uses ringA(f0x), ringB(f1x)
    float ringA[11], ringB[11], ringC[11];
#pragma unroll
    for (int i = 0; i < 11; ++i) { ringA[i] = 0.f; ringB[i] = 0.f; ringC[i] = 0.f; }

    float v0 = 0.f, v1 = 0.f, v2 = 0.f, v3 = 0.f;
    float n0 = 0.f, n1 = 0.f, n2 = 0.f, n3 = 0.f;
    float p0 = 0.f, p1 = 0.f;
    float2 m0 = make_float2(0.f,0.f), m1 = m0, m2 = m0;
    float2 nm0 = m0, nm1 = m0;
    float s0 = 0.f, s1 = 0.f, s2 = 0.f;

    // preload strip first row
    if (isA) {
        const int o = r0s*WW + c;
        v0 = xp[o]; v3 = fq2[o];
    } else {
        const int o = r0s*WW + c;
        v0 = xp[o]; v1 = fq0[o]; v2 = fq1[o];
    }

    {   // warm-up 11 rows (compile-time pruned ring guards)
        const int rbase = r0s;
        ROWM(0,1) ROWM(1,1) ROWM(2,1) ROWM(3,1) ROWM(4,1) ROWM(5,1)
        ROWM(6,1) ROWM(7,1) ROWM(8,1) ROWM(9,1) ROWM(10,1)
    }
    for (int rbase = r0s + 11; rbase < rend; rbase += 11) {
        ROWM(0,0) ROWM(1,0) ROWM(2,0) ROWM(3,0) ROWM(4,0) ROWM(5,0)
        ROWM(6,0) ROWM(7,0) ROWM(8,0) ROWM(9,0) ROWM(10,0)
    }

    // flush: team B consumes the last pending output row
    __syncthreads();
    if (!isA && c < OW) {
        const float2 ex = sex[(rend-1) & 1][c];
        const float mux = ex.x, mux2 = ex.x*ex.x, c2s = ex.y + SSIM_C2;
        SSJ(m0.x, m0.y, p0, s0)
        SSJ(m1.x, m1.y, p1, s1)
    }

    // reduce and write per-strip partials (no atomics)
    const float inv = 1.0f / (float)(OH * OW);
    if (isA) {
        float t2 = s2 * inv;
#pragma unroll
        for (int off = 16; off; off >>= 1)
            t2 += __shfl_down_sync(0xFFFFFFFFu, t2, off);
        if ((tid & 31) == 0) wredA[tid >> 5] = t2;
    } else {
        float t0 = s0 * inv, t1 = s1 * inv;
#pragma unroll
        for (int off = 16; off; off >>= 1) {
            t0 += __shfl_down_sync(0xFFFFFFFFu, t0, off);
            t1 += __shfl_down_sync(0xFFFFFFFFu, t1, off);
        }
        const int fw = (tid - 192) >> 5;
        if ((tid & 31) == 0) { wredB[fw][0] = t0; wredB[fw][1] = t1; }
    }
    __syncthreads();
    if (tid == 0) {
        float q0 = 0.f, q1 = 0.f, q2 = 0.f;
#pragma unroll
        for (int w = 0; w < 6; ++w) {
            q0 += wredB[w][0]; q1 += wredB[w][1]; q2 += wredA[w];
        }
        g_part[blockIdx.y][(b*3 + 0)*NC + ch] = q0;
        g_part[blockIdx.y][(b*3 + 1)*NC + ch] = q1;
        g_part[blockIdx.y][(b*3 + 2)*NC + ch] = q2;
    }
}

// ---------------------------------------------------------------------------
// Kernel 3: sum strip partials; emit ssim_info to out[512:2048]; spatial gate
// conv (3,1) over C, relu, MLP 64->64->64 (float4 weight loads), sigmoid.
// ---------------------------------------------------------------------------
__global__ void __launch_bounds__(64) epilogue_kernel(
    const float* __restrict__ sw,
    const float* __restrict__ W1, const float* __restrict__ b1,
    const float* __restrict__ W2, const float* __restrict__ b2,
    float* __restrict__ out, int out_size)
{
    const int b = blockIdx.x;
    const int c = threadIdx.x;

    __shared__ float ss[3][66];     // zero-padded ssim_info for this b
    __shared__ float gate[64];
    __shared__ float h1s[64];

#pragma unroll
    for (int j = 0; j < 3; ++j) {
        const int idx = (b*3 + j)*NC + c;
        const float sj = g_part[0][idx] + g_part[1][idx];
        ss[j][c + 1] = sj;
        if (out_size >= 2048) out[512 + b*NF*NC + j*NC + c] = sj;
        if (c == 0)  ss[j][0]  = 0.f;
        if (c == 63) ss[j][65] = 0.f;
    }
    __syncthreads();

    float g = 0.f;
#pragma unroll
    for (int j = 0; j < 3; ++j)
#pragma unroll
        for (int d = 0; d < 3; ++d)
            g = fmaf(sw[j*3 + d], ss[j][c + d], g);
    gate[c] = fmaxf(g, 0.f);
    __syncthreads();

    const float4* W1v = reinterpret_cast<const float4*>(W1);
    float h1 = b1[c];
#pragma unroll
    for (int k = 0; k < 16; ++k) {
        const float4 w = W1v[c*16 + k];
        h1 = fmaf(w.x, gate[4*k+0], h1); h1 = fmaf(w.y, gate[4*k+1], h1);
        h1 = fmaf(w.z, gate[4*k+2], h1); h1 = fmaf(w.w, gate[4*k+3], h1);
    }
    h1s[c] = fmaxf(h1, 0.f);
    __syncthreads();

    const float4* W2v = reinterpret_cast<const float4*>(W2);
    float h2 = b2[c];
#pragma unroll
    for (int k = 0; k < 16; ++k) {
        const float4 w = W2v[c*16 + k];
        h2 = fmaf(w.x, h1s[4*k+0], h2); h2 = fmaf(w.y, h1s[4*k+1], h2);
        h2 = fmaf(w.z, h1s[4*k+2], h2); h2 = fmaf(w.w, h1s[4*k+3], h2);
    }
    out[b*64 + c] = 1.0f / (1.0f + expf(-h2));
}

// ---------------------------------------------------------------------------
extern "C" void kernel_launch(void* const* d_in, const int* in_sizes, int n_in,
                              void* d_out, int out_size)
{
    const float* x  = (const float*)d_in[0];
    const float* f  = (const float*)d_in[1];
    const float* sw = (const float*)d_in[2];
    const float* W1 = (const float*)d_in[3];
    const float* b1 = (const float*)d_in[4];
    const float* W2 = (const float*)d_in[5];
    const float* b2 = (const float*)d_in[6];
    float* out = (float*)d_out;

    f_moments_kernel<<<dim3(14, 24), 192>>>(f);
    ssim_main_kernel<<<dim3(NB*NC, 2), 384>>>(x, f);
    epilogue_kernel<<<NB, 64>>>(sw, W1, b1, W2, b2, out, out_size);
}

// round 8
// speedup vs baseline: 1.3776x; 1.2799x over previous
#include <cuda_runtime.h>
#include <cuda_fp16.h>
#include <math.h>

#define HH 192
#define WW 192
#define OH 182
#define OW 182
#define OHW (OH*OW)
#define NB 8
#define NC 64
#define NF 3

#define SSIM_C1 0.01f
#define SSIM_C2 0.09f

// 11-tap gaussian (sigma=1.5), normalized; fp32 literals keep FFMA-imm forms.
#define GW0 0.00102838f
#define GW1 0.00759876f
#define GW2 0.03600077f
#define GW3 0.10936069f
#define GW4 0.21300554f
#define GW5 0.26601173f

#define TAPS(M) M(0,GW0) M(1,GW1) M(2,GW2) M(3,GW3) M(4,GW4) M(5,GW5) \
                M(6,GW4) M(7,GW3) M(8,GW2) M(9,GW1) M(10,GW0)

// __device__ scratch (allocation-free rule)
__device__ float2 g_mf [NB*NF*OH*OW];    // {mu_f, sig_f}
__device__ float  g_part[2][NB*NF*NC];   // per-strip ssim partial sums

// ---------------------------------------------------------------------------
// Kernel 1: per-(b,f) gaussian moments {mu_f, sig_f}. Grid (14 strips, 24 ch).
// ---------------------------------------------------------------------------
__global__ void __launch_bounds__(192) f_moments_kernel(const float* __restrict__ f)
{
    const int s   = blockIdx.x;
    const int bj  = blockIdx.y;
    const int tid = threadIdx.x;
    const float* fp = f + (size_t)bj * HH * WW;
    const int o0   = s * 13;
    const int o1   = min(OH, o0 + 13);
    const int rend = o1 + 9;

    __shared__ float2 sp[2][192];
    float a0[11], a1[11];
#pragma unroll
    for (int i = 0; i < 11; ++i) { a0[i] = 0.f; a1[i] = 0.f; }

    float fv = fp[o0 * WW + tid];
    for (int r = o0; r <= rend; ++r) {
        const int buf = r & 1;
        sp[buf][tid] = make_float2(fv, fv * fv);
        float nfv = 0.f;
        if (r < rend) nfv = fp[(r + 1) * WW + tid];
        __syncthreads();
        if (tid < OW) {
            const float2* spb = sp[buf];
            float h0 = 0.f, h1 = 0.f;
#define K1H(k, GK) { float2 q = spb[tid + (k)]; h0 = fmaf((GK), q.x, h0); h1 = fmaf((GK), q.y, h1); }
            TAPS(K1H)
#undef K1H
#pragma unroll
            for (int j = 10; j >= 1; --j) { a0[j] = a0[j-1]; a1[j] = a1[j-1]; }
            a0[0] = 0.f; a1[0] = 0.f;
#define K1A(j, GJ) { a0[j] = fmaf((GJ), h0, a0[j]); a1[j] = fmaf((GJ), h1, a1[j]); }
            TAPS(K1A)
#undef K1A
            if (r - 10 >= o0) {
                const int o = r - 10;
                const float mu = a0[10];
                g_mf[bj * OHW + o * OW + tid] = make_float2(mu, a1[10] - mu * mu);
            }
        }
        fv = nfv;
    }
}

// ---------------------------------------------------------------------------
// Kernel 2: main SSIM (R4 topology, fp16 staging).
// Grid (512, 2): blockIdx.x = b*64+c, blockIdx.y = row strip (91 out rows).
// Team X (tid<192): stages {x,x^2} as half2, fp32 h-accumulate, publishes
//   {mu_x, sig_x}. Team F: stages {f0x,f1x | f2x,0} as half4, HFMA2
//   h-accumulate, v-rings fp32, consumes SSIM with one-row lag.
// One __syncthreads per row.
// ---------------------------------------------------------------------------

struct alignas(8) H4 { __half2 q, r; };

// ring slot for output row (q - t), PH = within-strip phase mod 11
#define RS(PH,t) (((PH) + 22 - (t)) % 11)

#define XT(k,G) { float2 qv = __half22float2(bp[c + (k)]); \
    h0 = fmaf((G), qv.x, h0); h1 = fmaf((G), qv.y, h1); }

#define FT(k,WH) { H4 t4 = bp[c + (k)]; \
    hq = __hfma2((WH), t4.q, hq); hr = __hfma2((WH), t4.r, hr); }

#define _XV(PH,t,G,W) { if (!(W) || (PH) >= (t)) { \
    ringA[RS(PH,t)] = fmaf((G), h0, ringA[RS(PH,t)]); \
    ringB[RS(PH,t)] = fmaf((G), h1, ringB[RS(PH,t)]); } }

#define _FV(PH,t,G,W) { if (!(W) || (PH) >= (t)) { \
    ringA[RS(PH,t)] = fmaf((G), h2, ringA[RS(PH,t)]); \
    ringB[RS(PH,t)] = fmaf((G), h3, ringB[RS(PH,t)]); \
    ringD[RS(PH,t)] = fmaf((G), h4, ringD[RS(PH,t)]); } }

#define XV(PH,W) _XV(PH,0,GW0,W) _XV(PH,1,GW1,W) _XV(PH,2,GW2,W) _XV(PH,3,GW3,W) \
                 _XV(PH,4,GW4,W) _XV(PH,5,GW5,W) _XV(PH,6,GW4,W) _XV(PH,7,GW3,W) \
                 _XV(PH,8,GW2,W) _XV(PH,9,GW1,W) _XV(PH,10,GW0,W)
#define FV(PH,W) _FV(PH,0,GW0,W) _FV(PH,1,GW1,W) _FV(PH,2,GW2,W) _FV(PH,3,GW3,W) \
                 _FV(PH,4,GW4,W) _FV(PH,5,GW5,W) _FV(PH,6,GW4,W) _FV(PH,7,GW3,W) \
                 _FV(PH,8,GW2,W) _FV(PH,9,GW1,W) _FV(PH,10,GW0,W)

#define SSJ(MU,SG,P,S) { \
    const float mm  = (MU) * mux; \
    const float num = (2.f*mm + SSIM_C1) * (2.f*((P) - mm) + SSIM_C2); \
    const float den = (fmaf((MU),(MU),mux2) + SSIM_C1) * ((SG) + c2s); \
    S += __fdividef(num, den); }

#define ROW(PH, WARMF) { \
    const int r = rbase + (PH); \
    if (r < rend) { \
        const int buf = r & 1; \
        if (isX) { \
            sP[buf][c] = __floats2half2_rn(v0, v0*v0); \
            n0 = 0.f; \
            if (r + 1 < rend) n0 = xp[(r+1)*WW + c]; \
        } else { \
            H4 st; st.q = __floats2half2_rn(v1*v0, v2*v0); \
            st.r = __floats2half2_rn(v3*v0, 0.f); \
            sF[buf][c] = st; \
            n0 = 0.f; n1 = 0.f; n2 = 0.f; n3 = 0.f; \
            if (r + 1 < rend) { const int no = (r+1)*WW + c; \
                n0 = xp[no]; n1 = fq0[no]; n2 = fq1[no]; n3 = fq2[no]; } \
            if ((!(WARMF) || (PH) >= 10) && c < OW) { \
                const int mbase = (r-10)*OW + c; \
                nm0 = g_mf[mb0+mbase]; nm1 = g_mf[mb1+mbase]; nm2 = g_mf[mb2+mbase]; } \
        } \
        __syncthreads(); \
        if (c < OW) { \
            if (isX) { \
                float h0 = 0.f, h1 = 0.f; \
                { const __half2* bp = sP[buf]; TAPS(XT) } \
                XV(PH, WARMF) \
                if (!(WARMF) || (PH) == 10) { \
                    const int e = ((PH)+1) % 11; \
                    const float mu = ringA[e]; \
                    sex[buf][c] = make_float2(mu, ringB[e] - mu*mu); \
                    ringA[e] = 0.f; ringB[e] = 0.f; } \
            } else { \
                __half2 hq = __float2half2_rn(0.f), hr = hq; \
                { const H4* bp = sF[buf]; \
                  FT(0,W0h) FT(1,W1h) FT(2,W2h) FT(3,W3h) FT(4,W4h) FT(5,W5h) \
                  FT(6,W4h) FT(7,W3h) FT(8,W2h) FT(9,W1h) FT(10,W0h) } \
                const float2 q01 = __half22float2(hq); \
                const float h2 = q01.x, h3 = q01.y, h4 = __low2float(hr); \
                FV(PH, WARMF) \
                if (!(WARMF)) { \
                    const float2 ex = sex[buf ^ 1][c]; \
                    const float mux = ex.x, mux2 = ex.x*ex.x, c2s = ex.y + SSIM_C2; \
                    SSJ(m0.x, m0.y, p0, s0) \
                    SSJ(m1.x, m1.y, p1, s1) \
                    SSJ(m2.x, m2.y, p2, s2) } \
                if (!(WARMF) || (PH) == 10) { \
                    const int e = ((PH)+1) % 11; \
                    p0 = ringA[e]; p1 = ringB[e]; p2 = ringD[e]; \
                    ringA[e] = 0.f; ringB[e] = 0.f; ringD[e] = 0.f; \
                    m0 = nm0; m1 = nm1; m2 = nm2; } \
            } \
        } \
        if (isX) { v0 = n0; } else { v0 = n0; v1 = n1; v2 = n2; v3 = n3; } \
    } }

__global__ void __launch_bounds__(384, 2) ssim_main_kernel(
    const float* __restrict__ x, const float* __restrict__ f)
{
    const int bc  = blockIdx.x;          // b*64 + c
    const int b   = bc >> 6;
    const int ch  = bc & 63;
    const int tid = threadIdx.x;
    const bool isX = tid < 192;
    const int c   = isX ? tid : tid - 192;

    const int r0s  = blockIdx.y * 91;    // strip input start
    const int rend = r0s + 101;          // strip input end (exclusive)

    const float* xp  = x + (size_t)bc * HH * WW;
    const float* fq0 = f + (size_t)(b*3 + 0) * HH * WW;
    const float* fq1 = f + (size_t)(b*3 + 1) * HH * WW;
    const float* fq2 = f + (size_t)(b*3 + 2) * HH * WW;
    const int mb0 = (b*3 + 0) * OHW;
    const int mb1 = (b*3 + 1) * OHW;
    const int mb2 = (b*3 + 2) * OHW;

    __shared__ __half2 sP[2][192];       // {x, x^2} in fp16
    __shared__ H4      sF[2][192];       // {f0x, f1x | f2x, 0} in fp16
    __shared__ float2  sex[2][192];      // exchange {mu_x, sig_x} (fp32)
    __shared__ float   wredF[6][3];

    const __half2 W0h = __float2half2_rn(GW0), W1h = __float2half2_rn(GW1);
    const __half2 W2h = __float2half2_rn(GW2), W3h = __float2half2_rn(GW3);
    const __half2 W4h = __float2half2_rn(GW4), W5h = __float2half2_rn(GW5);

    // vertical rings (fp32): X uses ringA(x), ringB(x^2); F uses ringA(f0x),
    // ringB(f1x), ringD(f2x)
    float ringA[11], ringB[11], ringD[11];
#pragma unroll
    for (int i = 0; i < 11; ++i) { ringA[i] = 0.f; ringB[i] = 0.f; ringD[i] = 0.f; }

    float v0 = 0.f, v1 = 0.f, v2 = 0.f, v3 = 0.f;
    float n0 = 0.f, n1 = 0.f, n2 = 0.f, n3 = 0.f;
    float p0 = 0.f, p1 = 0.f, p2 = 0.f;
    float2 m0 = make_float2(0.f,0.f), m1 = m0, m2 = m0;
    float2 nm0 = m0, nm1 = m0, nm2 = m0;
    float s0 = 0.f, s1 = 0.f, s2 = 0.f;

    // preload strip first row
    if (isX) {
        v0 = xp[r0s*WW + c];
    } else {
        const int o = r0s*WW + c;
        v0 = xp[o]; v1 = fq0[o]; v2 = fq1[o]; v3 = fq2[o];
    }

    {   // warm-up 11 rows (compile-time pruned ring guards; no SSIM consume)
        const int rbase = r0s;
        ROW(0,1) ROW(1,1) ROW(2,1) ROW(3,1) ROW(4,1) ROW(5,1)
        ROW(6,1) ROW(7,1) ROW(8,1) ROW(9,1) ROW(10,1)
    }
    for (int rbase = r0s + 11; rbase < rend; rbase += 11) {
        ROW(0,0) ROW(1,0) ROW(2,0) ROW(3,0) ROW(4,0) ROW(5,0)
        ROW(6,0) ROW(7,0) ROW(8,0) ROW(9,0) ROW(10,0)
    }

    // flush: consume the last pending output row (uses sex written at rend-1)
    __syncthreads();
    if (!isX && c < OW) {
        const float2 ex = sex[(rend-1) & 1][c];
        const float mux = ex.x, mux2 = ex.x*ex.x, c2s = ex.y + SSIM_C2;
        SSJ(m0.x, m0.y, p0, s0)
        SSJ(m1.x, m1.y, p1, s1)
        SSJ(m2.x, m2.y, p2, s2)
    }

    // reduce the 3 sums over team F; write per-strip partial (no atomics)
    if (!isX) {
        const float inv = 1.0f / (float)(OH * OW);
        float t0 = s0 * inv, t1 = s1 * inv, t2 = s2 * inv;
#pragma unroll
        for (int off = 16; off; off >>= 1) {
            t0 += __shfl_down_sync(0xFFFFFFFFu, t0, off);
            t1 += __shfl_down_sync(0xFFFFFFFFu, t1, off);
            t2 += __shfl_down_sync(0xFFFFFFFFu, t2, off);
        }
        const int fw = (tid - 192) >> 5, lane = tid & 31;
        if (lane == 0) { wredF[fw][0] = t0; wredF[fw][1] = t1; wredF[fw][2] = t2; }
    }
    __syncthreads();
    if (tid == 192) {
        float q0 = 0.f, q1 = 0.f, q2 = 0.f;
#pragma unroll
        for (int w = 0; w < 6; ++w) { q0 += wredF[w][0]; q1 += wredF[w][1]; q2 += wredF[w][2]; }
        g_part[blockIdx.y][(b*3 + 0)*NC + ch] = q0;
        g_part[blockIdx.y][(b*3 + 1)*NC + ch] = q1;
        g_part[blockIdx.y][(b*3 + 2)*NC + ch] = q2;
    }
}

// ---------------------------------------------------------------------------
// Kernel 3: sum strip partials; emit ssim_info to out[512:2048]; spatial gate
// conv (3,1) over C, relu, MLP 64->64->64 (float4 weight loads), sigmoid.
// ---------------------------------------------------------------------------
__global__ void __launch_bounds__(64) epilogue_kernel(
    const float* __restrict__ sw,
    const float* __restrict__ W1, const float* __restrict__ b1,
    const float* __restrict__ W2, const float* __restrict__ b2,
    float* __restrict__ out, int out_size)
{
    const int b = blockIdx.x;
    const int c = threadIdx.x;

    __shared__ float ss[3][66];     // zero-padded ssim_info for this b
    __shared__ float gate[64];
    __shared__ float h1s[64];

#pragma unroll
    for (int j = 0; j < 3; ++j) {
        const int idx = (b*3 + j)*NC + c;
        const float sj = g_part[0][idx] + g_part[1][idx];
        ss[j][c + 1] = sj;
        if (out_size >= 2048) out[512 + b*NF*NC + j*NC + c] = sj;
        if (c == 0)  ss[j][0]  = 0.f;
        if (c == 63) ss[j][65] = 0.f;
    }
    __syncthreads();

    float g = 0.f;
#pragma unroll
    for (int j = 0; j < 3; ++j)
#pragma unroll
        for (int d = 0; d < 3; ++d)
            g = fmaf(sw[j*3 + d], ss[j][c + d], g);
    gate[c] = fmaxf(g, 0.f);
    __syncthreads();

    const float4* W1v = reinterpret_cast<const float4*>(W1);
    float h1 = b1[c];
#pragma unroll
    for (int k = 0; k < 16; ++k) {
        const float4 w = W1v[c*16 + k];
        h1 = fmaf(w.x, gate[4*k+0], h1); h1 = fmaf(w.y, gate[4*k+1], h1);
        h1 = fmaf(w.z, gate[4*k+2], h1); h1 = fmaf(w.w, gate[4*k+3], h1);
    }
    h1s[c] = fmaxf(h1, 0.f);
    __syncthreads();

    const float4* W2v = reinterpret_cast<const float4*>(W2);
    float h2 = b2[c];
#pragma unroll
    for (int k = 0; k < 16; ++k) {
        const float4 w = W2v[c*16 + k];
        h2 = fmaf(w.x, h1s[4*k+0], h2); h2 = fmaf(w.y, h1s[4*k+1], h2);
        h2 = fmaf(w.z, h1s[4*k+2], h2); h2 = fmaf(w.w, h1s[4*k+3], h2);
    }
    out[b*64 + c] = 1.0f / (1.0f + expf(-h2));
}

// ---------------------------------------------------------------------------
extern "C" void kernel_launch(void* const* d_in, const int* in_sizes, int n_in,
                              void* d_out, int out_size)
{
    const float* x  = (const float*)d_in[0];
    const float* f  = (const float*)d_in[1];
    const float* sw = (const float*)d_in[2];
    const float* W1 = (const float*)d_in[3];
    const float* b1 = (const float*)d_in[4];
    const float* W2 = (const float*)d_in[5];
    const float* b2 = (const float*)d_in[6];
    float* out = (float*)d_out;

    f_moments_kernel<<<dim3(14, 24), 192>>>(f);
    ssim_main_kernel<<<dim3(NB*NC, 2), 384>>>(x, f);
    epilogue_kernel<<<NB, 64>>>(sw, W1, b1, W2, b2, out, out_size);
}